// round 16
// baseline (speedup 1.0000x reference)
#include <cuda_runtime.h>
#include <cstdint>
#include <cstddef>

#define TT   4096
#define EMBD 100
#define HIDN 512
#define G3   1536

typedef unsigned long long ull;

// ---------------- scratch (no cudaMalloc allowed) ----------------
__device__ float g_x[TT * EMBD];            // embedded inputs      (1.6 MB)
__device__ float g_y0[TT * 1024];           // layer-0 output       (16.8 MB)
__device__ float g_gi0[2 * TT * G3];        // layer-0 input gates  (50.3 MB)
__device__ float g_gi1[2 * TT * G3];        // layer-1 input gates  (50.3 MB)

// ---------------- helpers ----------------
__device__ __forceinline__ void cluster_sync_() {
    asm volatile("barrier.cluster.arrive.aligned;" ::: "memory");
    asm volatile("barrier.cluster.wait.aligned;" ::: "memory");
}

// bulk push: local smem stage -> peer CTA's smem, complete_tx on peer mbar
__device__ __forceinline__ void bulk_push(unsigned dst, unsigned src,
                                          unsigned mb, unsigned rank,
                                          unsigned bytes) {
    asm volatile(
        "{\n\t.reg .u32 rd, rb;\n\t"
        "mapa.shared::cluster.u32 rd, %0, %3;\n\t"
        "mapa.shared::cluster.u32 rb, %2, %3;\n\t"
        "cp.async.bulk.shared::cluster.shared::cta.mbarrier::complete_tx::bytes "
        "[rd], [%1], %4, [rb];\n\t}"
        :: "r"(dst), "r"(src), "r"(mb), "r"(rank), "r"(bytes) : "memory");
}

__device__ __forceinline__ void mbar_init(unsigned mb, unsigned cnt) {
    asm volatile("mbarrier.init.shared.b64 [%0], %1;" :: "r"(mb), "r"(cnt) : "memory");
}
__device__ __forceinline__ void mbar_arm(unsigned mb, unsigned tx) {
    asm volatile("mbarrier.arrive.expect_tx.shared.b64 _, [%0], %1;"
                 :: "r"(mb), "r"(tx) : "memory");
}
__device__ __forceinline__ void mbar_wait(unsigned mb, unsigned par) {
    unsigned done;
    asm volatile(
        "{\n\t.reg .pred p;\n\t"
        "mbarrier.try_wait.parity.acquire.cluster.shared::cta.b64 p, [%1], %2;\n\t"
        "selp.b32 %0, 1, 0, p;\n\t}"
        : "=r"(done) : "r"(mb), "r"(par) : "memory");
    while (!done) {
        asm volatile(
            "{\n\t.reg .pred p;\n\t"
            "mbarrier.try_wait.parity.acquire.cluster.shared::cta.b64 p, [%1], %2, 0x989680;\n\t"
            "selp.b32 %0, 1, 0, p;\n\t}"
            : "=r"(done) : "r"(mb), "r"(par) : "memory");
    }
}

__device__ __forceinline__ void fence_proxy_async_() {
    asm volatile("fence.proxy.async.shared::cta;" ::: "memory");
}

// packed f32x2 fma: acc = w * h + acc
#define FMA2(acc, w, h) \
    asm("fma.rn.f32x2 %0, %1, %2, %0;" : "+l"(acc) : "l"(w), "l"(h))

__device__ __forceinline__ float lo_f(ull v) {
    return __int_as_float((int)(unsigned)(v & 0xffffffffull));
}
__device__ __forceinline__ float hi_f(ull v) {
    return __int_as_float((int)(unsigned)(v >> 32));
}

// ---------------- embedding ----------------
__global__ void embed_kernel(const int* __restrict__ words,
                             const float* __restrict__ emb,
                             float* __restrict__ x) {
    int i = blockIdx.x * blockDim.x + threadIdx.x;
    if (i < TT * EMBD) {
        int t = i / EMBD, k = i % EMBD;
        x[i] = emb[(size_t)words[t] * EMBD + k];
    }
}

// ---------------- input-projection GEMM (R7 scalar, proven) ----------------
#define BM 128
#define BN 128
#define BK 16

__global__ void __launch_bounds__(256, 2) gemm_gi_kernel(
    const float* __restrict__ A, int M, int K,
    const float* __restrict__ Wf, const float* __restrict__ Wb,
    const float* __restrict__ bihf, const float* __restrict__ bhhf,
    const float* __restrict__ bihb, const float* __restrict__ bhhb,
    float* __restrict__ out)
{
    __shared__ float As[BK][BM + 4];
    __shared__ float Ws[BK][BN + 4];

    const int dir = blockIdx.z;
    const float* W   = dir ? Wb   : Wf;
    const float* bih = dir ? bihb : bihf;
    const float* bhh = dir ? bhhb : bhhf;

    const int n0 = blockIdx.x * BN;
    const int m0 = blockIdx.y * BM;
    const int tid = threadIdx.x;
    const int tx = tid & 15, ty = tid >> 4;

    float acc[8][8];
    #pragma unroll
    for (int i = 0; i < 8; i++)
        #pragma unroll
        for (int j = 0; j < 8; j++) acc[i][j] = 0.f;

    for (int k0 = 0; k0 < K; k0 += BK) {
        #pragma unroll
        for (int e = tid; e < BM * BK; e += 256) {
            int m = e >> 4, k = e & 15;
            int kk = k0 + k;
            As[k][m] = (kk < K) ? A[(size_t)(m0 + m) * K + kk] : 0.f;
        }
        #pragma unroll
        for (int e = tid; e < BN * BK; e += 256) {
            int n = e >> 4, k = e & 15;
            int kk = k0 + k;
            Ws[k][n] = (kk < K) ? W[(size_t)(n0 + n) * K + kk] : 0.f;
        }
        __syncthreads();
        #pragma unroll
        for (int k = 0; k < BK; k++) {
            float a[8], b[8];
            #pragma unroll
            for (int i = 0; i < 8; i++) a[i] = As[k][ty * 8 + i];
            #pragma unroll
            for (int i = 0; i < 8; i++) b[i] = Ws[k][tx * 8 + i];
            #pragma unroll
            for (int i = 0; i < 8; i++)
                #pragma unroll
                for (int j = 0; j < 8; j++)
                    acc[i][j] += a[i] * b[j];
        }
        __syncthreads();
    }

    #pragma unroll
    for (int i = 0; i < 8; i++) {
        int m = m0 + ty * 8 + i;
        #pragma unroll
        for (int j = 0; j < 8; j++) {
            int n = n0 + tx * 8 + j;
            float v = acc[i][j] + bih[n] + (n < 1024 ? bhh[n] : 0.f);
            out[(size_t)dir * M * G3 + (size_t)m * G3 + n] = v;
        }
    }
}

// ---------------- recurrent layer: hybrid broadcast scheme ----------------
// 32 CTAs = 2 clusters of 16 (fwd/bwd). CTA crank owns outputs
// [32*crank, 32*crank+32). Full h (512) lives in every CTA, double-buffered.
// Weights register-resident: warp w owns outputs j0=32*crank+2w, j0+1.
// Per step: mbar wait -> 8x LDS.64 h -> 48 fma.rn.f32x2 -> butterfly ->
// gates on lanes 0..1 -> stage own 32-value slice (128B) -> __syncthreads ->
// warp0 lanes 0..15 EACH push the 128B slice to one peer CTA (16 parallel
// bulks, complete_tx on peer mbar; 16 arrivals per destination buffer).
// Arm schedule (R5-proven): init arms buffer 1 only (step-0 pushes); step s
// arms buffer (s&1) for the step-(s+1) pushes. Each phase armed exactly once.
__global__ void __launch_bounds__(512, 1) gru_layer_kernel(
    const float* __restrict__ gi,                 // [2][T][1536]
    const float* __restrict__ whf, const float* __restrict__ whb,
    const float* __restrict__ bhf, const float* __restrict__ bhb,
    float* __restrict__ y_out,                    // [T][1024]
    float* __restrict__ state_out)                // [2][512]
{
    __shared__ __align__(16) float hbuf[2][512];          // full h, x2
    __shared__ __align__(16) float stage[2][32];          // own slice, x2
    __shared__ __align__(8) ull mbar[2];                  // one per h buffer

    const int crank = blockIdx.x & 15;
    const int dir   = blockIdx.x >> 4;
    const int tid   = threadIdx.x;
    const int warp  = tid >> 5;
    const int lane  = tid & 31;

    const float* w_hh = dir ? whb : whf;
    const float* b_hh = dir ? bhb : bhf;
    const float* gid  = gi + (size_t)dir * TT * G3;

    const int j0 = crank * 32 + 2 * warp;   // this warp's 2 global outputs

    // ---- weights into registers: rows (gate, j0 / j0+1) over full k ----
    ull w[48];
    #pragma unroll
    for (int r = 0; r < 6; r++) {
        const int jj   = j0 + (r >= 3 ? 1 : 0);
        const int gate = r % 3;
        const float* base = w_hh + (size_t)(gate * HIDN + jj) * HIDN + 2 * lane;
        #pragma unroll
        for (int p = 0; p < 8; p++)
            w[r * 8 + p] = *(const ull*)(base + 64 * p);
    }

    hbuf[0][tid] = 0.f;
    hbuf[1][tid] = 0.f;
    const float bhn = (lane < 2) ? b_hh[1024 + j0 + lane] : 0.f;

    const unsigned hbase = (unsigned)__cvta_generic_to_shared(hbuf);
    const unsigned stgb  = (unsigned)__cvta_generic_to_shared(stage);
    const unsigned mbb   = (unsigned)__cvta_generic_to_shared(mbar);
    const unsigned TXB   = 16u * 128u;      // 16 slices x 128 B per buffer

    if (tid == 0) {
        mbar_init(mbb, 1);
        mbar_init(mbb + 8, 1);
        mbar_arm(mbb + 8, TXB);      // buffer 1 <- step-0 pushes (ONLY this)
    }

    // gi walk (lanes 0..1 own the 2 outputs' gate scalars)
    const int t0    = dir ? TT - 1 : 0;
    const int gstep = dir ? -G3 : G3;
    const float* gp = gid + (size_t)t0 * G3 + j0 + lane;
    float gr = 0.f, gz = 0.f, gn = 0.f;
    if (lane < 2) { gr = gp[0]; gz = gp[512]; gn = gp[1024]; }

    float* yp = y_out + (size_t)t0 * 1024 + dir * 512 + j0 + lane;
    const int ystep = dir ? -1024 : 1024;

    __syncthreads();
    cluster_sync_();    // mbarriers + hbuf zeros visible cluster-wide

    for (int s = 0; s < TT; s++) {
        const int b   = s & 1;
        const int nxt = b ^ 1;

        // wait for all peers' step-(s-1) h slices into buffer b
        if (s > 0) mbar_wait(mbb + (unsigned)(b * 8),
                             ((unsigned)(s - 1) >> 1) & 1u);
        if (tid == 0) mbar_arm(mbb + (unsigned)(b * 8), TXB);  // step-(s+1) pushes

        float hprev = (lane < 2) ? hbuf[b][j0 + lane] : 0.f;

        // ---- 48 packed FMAs against full h from SMEM ----
        const ull* h2 = (const ull*)hbuf[b] + lane;
        ull a0 = 0, a1 = 0, a2 = 0, a3 = 0, a4 = 0, a5 = 0;
        #pragma unroll
        for (int p = 0; p < 8; p++) {
            ull hv = h2[32 * p];
            FMA2(a0, w[0 * 8 + p], hv);
            FMA2(a1, w[1 * 8 + p], hv);
            FMA2(a2, w[2 * 8 + p], hv);
            FMA2(a3, w[3 * 8 + p], hv);
            FMA2(a4, w[4 * 8 + p], hv);
            FMA2(a5, w[5 * 8 + p], hv);
        }

        // prefetch gi for step s+1 (hidden behind butterfly + inter-step wait)
        float ngr = 0.f, ngz = 0.f, ngn = 0.f;
        if (lane < 2 && s + 1 < TT) {
            const float* g2 = gp + gstep;
            ngr = g2[0]; ngz = g2[512]; ngn = g2[1024];
        }

        float s0 = lo_f(a0) + hi_f(a0);
        float s1 = lo_f(a1) + hi_f(a1);
        float s2 = lo_f(a2) + hi_f(a2);
        float s3 = lo_f(a3) + hi_f(a3);
        float s4 = lo_f(a4) + hi_f(a4);
        float s5 = lo_f(a5) + hi_f(a5);

        #pragma unroll
        for (int off = 16; off; off >>= 1) {
            s0 += __shfl_xor_sync(0xffffffffu, s0, off);
            s1 += __shfl_xor_sync(0xffffffffu, s1, off);
            s2 += __shfl_xor_sync(0xffffffffu, s2, off);
            s3 += __shfl_xor_sync(0xffffffffu, s3, off);
            s4 += __shfl_xor_sync(0xffffffffu, s4, off);
            s5 += __shfl_xor_sync(0xffffffffu, s5, off);
        }

        if (lane < 2) {
            const float ar = lane ? s3 : s0;
            const float az = lane ? s4 : s1;
            const float an = lane ? s5 : s2;
            float rg = 1.f / (1.f + __expf(-(gr + ar)));
            float zg = 1.f / (1.f + __expf(-(gz + az)));
            float u  = gn + rg * (an + bhn);
            float e2 = __expf(2.f * u);
            float ng = 1.f - 2.f / (e2 + 1.f);       // tanh(u), inf-safe
            float hnew = ng + zg * (hprev - ng);

            stage[nxt][2 * warp + lane] = hnew;      // own-slice staging
            *yp = hnew;
            if (s == TT - 1) state_out[dir * 512 + j0 + lane] = hnew;

            gr = ngr; gz = ngz; gn = ngn;
        }
        gp += gstep; yp += ystep;

        __syncthreads();    // all 32 slice values staged; hbuf[b] reads done

        // 16 parallel 128B pushes: lane l of warp0 -> peer CTA l
        if (warp == 0 && lane < 16 && s + 1 < TT) {
            fence_proxy_async_();
            bulk_push(hbase + (unsigned)((nxt * 512 + crank * 32) * 4),
                      stgb + (unsigned)(nxt * 128),
                      mbb + (unsigned)(nxt * 8),
                      (unsigned)lane, 128u);
        }
    }

    cluster_sync_();    // keep smem alive until all in-flight pushes landed
}

// ---------------- launch ----------------
static void launch_gru(const float* gi,
                       const float* whf, const float* whb,
                       const float* bhf, const float* bhb,
                       float* y_out, float* state_out) {
    cudaFuncSetAttribute(gru_layer_kernel,
                         cudaFuncAttributeNonPortableClusterSizeAllowed, 1);

    cudaLaunchConfig_t cfg = {};
    cfg.gridDim = dim3(32, 1, 1);
    cfg.blockDim = dim3(512, 1, 1);
    cfg.dynamicSmemBytes = 0;
    cfg.stream = 0;
    cudaLaunchAttribute attr[1];
    attr[0].id = cudaLaunchAttributeClusterDimension;
    attr[0].val.clusterDim.x = 16;
    attr[0].val.clusterDim.y = 1;
    attr[0].val.clusterDim.z = 1;
    cfg.attrs = attr;
    cfg.numAttrs = 1;

    cudaLaunchKernelEx(&cfg, gru_layer_kernel, gi, whf, whb, bhf, bhb, y_out, state_out);
}

extern "C" void kernel_launch(void* const* d_in, const int* in_sizes, int n_in,
                              void* d_out, int out_size) {
    const int*   words    = (const int*)d_in[0];
    const float* emb      = (const float*)d_in[1];
    const float* w_ih_l0f = (const float*)d_in[2];
    const float* w_hh_l0f = (const float*)d_in[3];
    const float* b_ih_l0f = (const float*)d_in[4];
    const float* b_hh_l0f = (const float*)d_in[5];
    const float* w_ih_l0b = (const float*)d_in[6];
    const float* w_hh_l0b = (const float*)d_in[7];
    const float* b_ih_l0b = (const float*)d_in[8];
    const float* b_hh_l0b = (const float*)d_in[9];
    const float* w_ih_l1f = (const float*)d_in[10];
    const float* w_hh_l1f = (const float*)d_in[11];
    const float* b_ih_l1f = (const float*)d_in[12];
    const float* b_hh_l1f = (const float*)d_in[13];
    const float* w_ih_l1b = (const float*)d_in[14];
    const float* w_hh_l1b = (const float*)d_in[15];
    const float* b_ih_l1b = (const float*)d_in[16];
    const float* b_hh_l1b = (const float*)d_in[17];
    float* out = (float*)d_out;

    float *px, *py0, *pgi0, *pgi1;
    cudaGetSymbolAddress((void**)&px,   g_x);
    cudaGetSymbolAddress((void**)&py0,  g_y0);
    cudaGetSymbolAddress((void**)&pgi0, g_gi0);
    cudaGetSymbolAddress((void**)&pgi1, g_gi1);

    // 1) embedding
    embed_kernel<<<(TT * EMBD + 255) / 256, 256>>>(words, emb, px);

    // 2) layer-0 input projections (both directions)
    dim3 gg(G3 / BN, TT / BM, 2);
    gemm_gi_kernel<<<gg, 256>>>(px, TT, EMBD,
                                w_ih_l0f, w_ih_l0b,
                                b_ih_l0f, b_hh_l0f, b_ih_l0b, b_hh_l0b, pgi0);

    // 3) layer-0 recurrence
    launch_gru(pgi0, w_hh_l0f, w_hh_l0b, b_hh_l0f, b_hh_l0b,
               py0, out + (size_t)TT * 1024);

    // 4) layer-1 input projections
    gemm_gi_kernel<<<gg, 256>>>(py0, TT, 1024,
                                w_ih_l1f, w_ih_l1b,
                                b_ih_l1f, b_hh_l1f, b_ih_l1b, b_hh_l1b, pgi1);

    // 5) layer-1 recurrence
    launch_gru(pgi1, w_hh_l1f, w_hh_l1b, b_hh_l1f, b_hh_l1b,
               out, out + (size_t)TT * 1024 + 1024);
}

// round 17
// speedup vs baseline: 1.5205x; 1.5205x over previous
#include <cuda_runtime.h>
#include <cstdint>
#include <cstddef>

#define TT   4096
#define EMBD 100
#define HIDN 512
#define G3   1536

typedef unsigned long long ull;

// ---------------- scratch (no cudaMalloc allowed) ----------------
__device__ float g_x[TT * EMBD];            // embedded inputs      (1.6 MB)
__device__ float g_y0[TT * 1024];           // layer-0 output       (16.8 MB)
__device__ float g_gi0[2 * TT * G3];        // layer-0 input gates  (50.3 MB)
__device__ float g_gi1[2 * TT * G3];        // layer-1 input gates  (50.3 MB)

// ---------------- helpers ----------------
__device__ __forceinline__ void cluster_sync_() {
    asm volatile("barrier.cluster.arrive.aligned;" ::: "memory");
    asm volatile("barrier.cluster.wait.aligned;" ::: "memory");
}

// 384B bulk push: local smem stage -> peer CTA's smem, complete_tx on peer mbar
__device__ __forceinline__ void bulk_push(unsigned dst, unsigned src,
                                          unsigned mb, unsigned rank,
                                          unsigned bytes) {
    asm volatile(
        "{\n\t.reg .u32 rd, rb;\n\t"
        "mapa.shared::cluster.u32 rd, %0, %3;\n\t"
        "mapa.shared::cluster.u32 rb, %2, %3;\n\t"
        "cp.async.bulk.shared::cluster.shared::cta.mbarrier::complete_tx::bytes "
        "[rd], [%1], %4, [rb];\n\t}"
        :: "r"(dst), "r"(src), "r"(mb), "r"(rank), "r"(bytes) : "memory");
}

__device__ __forceinline__ void mbar_init(unsigned mb, unsigned cnt) {
    asm volatile("mbarrier.init.shared.b64 [%0], %1;" :: "r"(mb), "r"(cnt) : "memory");
}
__device__ __forceinline__ void mbar_arm(unsigned mb, unsigned tx) {
    asm volatile("mbarrier.arrive.expect_tx.shared.b64 _, [%0], %1;"
                 :: "r"(mb), "r"(tx) : "memory");
}
__device__ __forceinline__ void mbar_wait(unsigned mb, unsigned par) {
    unsigned done;
    asm volatile(
        "{\n\t.reg .pred p;\n\t"
        "mbarrier.try_wait.parity.acquire.cluster.shared::cta.b64 p, [%1], %2;\n\t"
        "selp.b32 %0, 1, 0, p;\n\t}"
        : "=r"(done) : "r"(mb), "r"(par) : "memory");
    while (!done) {
        asm volatile(
            "{\n\t.reg .pred p;\n\t"
            "mbarrier.try_wait.parity.acquire.cluster.shared::cta.b64 p, [%1], %2, 0x989680;\n\t"
            "selp.b32 %0, 1, 0, p;\n\t}"
            : "=r"(done) : "r"(mb), "r"(par) : "memory");
    }
}

__device__ __forceinline__ void fence_proxy_async_() {
    asm volatile("fence.proxy.async.shared::cta;" ::: "memory");
}

// packed f32x2 fma: acc = w * h + acc
#define FMA2(acc, w, h) \
    asm("fma.rn.f32x2 %0, %1, %2, %0;" : "+l"(acc) : "l"(w), "l"(h))

__device__ __forceinline__ float lo_f(ull v) {
    return __int_as_float((int)(unsigned)(v & 0xffffffffull));
}
__device__ __forceinline__ float hi_f(ull v) {
    return __int_as_float((int)(unsigned)(v >> 32));
}

// ---------------- embedding ----------------
__global__ void embed_kernel(const int* __restrict__ words,
                             const float* __restrict__ emb,
                             float* __restrict__ x) {
    int i = blockIdx.x * blockDim.x + threadIdx.x;
    if (i < TT * EMBD) {
        int t = i / EMBD, k = i % EMBD;
        x[i] = emb[(size_t)words[t] * EMBD + k];
    }
}

// ---------------- input-projection GEMM (R7 scalar, proven) ----------------
#define BM 128
#define BN 128
#define BK 16

__global__ void __launch_bounds__(256, 2) gemm_gi_kernel(
    const float* __restrict__ A, int M, int K,
    const float* __restrict__ Wf, const float* __restrict__ Wb,
    const float* __restrict__ bihf, const float* __restrict__ bhhf,
    const float* __restrict__ bihb, const float* __restrict__ bhhb,
    float* __restrict__ out)
{
    __shared__ float As[BK][BM + 4];
    __shared__ float Ws[BK][BN + 4];

    const int dir = blockIdx.z;
    const float* W   = dir ? Wb   : Wf;
    const float* bih = dir ? bihb : bihf;
    const float* bhh = dir ? bhhb : bhhf;

    const int n0 = blockIdx.x * BN;
    const int m0 = blockIdx.y * BM;
    const int tid = threadIdx.x;
    const int tx = tid & 15, ty = tid >> 4;

    float acc[8][8];
    #pragma unroll
    for (int i = 0; i < 8; i++)
        #pragma unroll
        for (int j = 0; j < 8; j++) acc[i][j] = 0.f;

    for (int k0 = 0; k0 < K; k0 += BK) {
        #pragma unroll
        for (int e = tid; e < BM * BK; e += 256) {
            int m = e >> 4, k = e & 15;
            int kk = k0 + k;
            As[k][m] = (kk < K) ? A[(size_t)(m0 + m) * K + kk] : 0.f;
        }
        #pragma unroll
        for (int e = tid; e < BN * BK; e += 256) {
            int n = e >> 4, k = e & 15;
            int kk = k0 + k;
            Ws[k][n] = (kk < K) ? W[(size_t)(n0 + n) * K + kk] : 0.f;
        }
        __syncthreads();
        #pragma unroll
        for (int k = 0; k < BK; k++) {
            float a[8], b[8];
            #pragma unroll
            for (int i = 0; i < 8; i++) a[i] = As[k][ty * 8 + i];
            #pragma unroll
            for (int i = 0; i < 8; i++) b[i] = Ws[k][tx * 8 + i];
            #pragma unroll
            for (int i = 0; i < 8; i++)
                #pragma unroll
                for (int j = 0; j < 8; j++)
                    acc[i][j] += a[i] * b[j];
        }
        __syncthreads();
    }

    #pragma unroll
    for (int i = 0; i < 8; i++) {
        int m = m0 + ty * 8 + i;
        #pragma unroll
        for (int j = 0; j < 8; j++) {
            int n = n0 + tx * 8 + j;
            float v = acc[i][j] + bih[n] + (n < 1024 ? bhh[n] : 0.f);
            out[(size_t)dir * M * G3 + (size_t)m * G3 + n] = v;
        }
    }
}

// ---------------- recurrent layer: reduce-scatter (R7 + phase-3 fixes) ----
// 32 CTAs = 2 clusters of 16 (fwd/bwd). CTA c owns h-slice k=[32c,32c+32).
// Stage/pbuf layout per (warp|src, buf) is GATE-MAJOR:
//   [0:32) r-partials, [32:64) z-partials, [64:96) n-partials
// so every STS/LDS in phase 2/3 is stride-1 conflict-free.
// Phase 3 reduce is distributed over warps 0..2 (warp g sums gate g for all
// 32 outputs), combined via gsum + bar.sync(1,96); gates stay on warp0.
__global__ void __launch_bounds__(512, 1) gru_layer_kernel(
    const float* __restrict__ gi,                 // [2][T][1536]
    const float* __restrict__ whf, const float* __restrict__ whb,
    const float* __restrict__ bhf, const float* __restrict__ bhb,
    float* __restrict__ y_out,                    // [T][1024]
    float* __restrict__ state_out)                // [2][512]
{
    __shared__ __align__(16) float hsl[2][32];            // local h slice x2
    __shared__ __align__(16) float stage[16][2][96];      // per-warp out, x2
    __shared__ __align__(16) float pbuf[2][16][96];       // incoming partials
    __shared__ __align__(16) float gsum[2][32];           // z,n combine buf
    __shared__ __align__(8) ull mbar[2];

    const int crank = blockIdx.x & 15;
    const int dir   = blockIdx.x >> 4;
    const int tid   = threadIdx.x;
    const int warp  = tid >> 5;
    const int lane  = tid & 31;

    const float* w_hh = dir ? whb : whf;
    const float* b_hh = dir ? bhb : bhf;
    const float* gid  = gi + (size_t)dir * TT * G3;

    const int jd = 32 * warp + lane;      // output whose partials we compute
    const int jo = 32 * crank + lane;     // own output (warp0 gate duty)

    // ---- weights: rows (g, jd) over k in [32*crank, 32*crank+32) ----
    ull w[48];
    #pragma unroll
    for (int g = 0; g < 3; g++) {
        const float* base = w_hh + (size_t)(g * HIDN + jd) * HIDN + 32 * crank;
        #pragma unroll
        for (int p = 0; p < 16; p++)
            w[g * 16 + p] = *(const ull*)(base + 2 * p);
    }

    if (tid < 32) { hsl[0][tid] = 0.f; hsl[1][tid] = 0.f; }
    const float bhn = (warp == 0) ? b_hh[1024 + jo] : 0.f;

    const unsigned stgb = (unsigned)__cvta_generic_to_shared(stage);
    const unsigned pbb  = (unsigned)__cvta_generic_to_shared(pbuf);
    const unsigned mbb  = (unsigned)__cvta_generic_to_shared(mbar);
    const unsigned TXB  = 16u * 384u;

    if (tid == 0) {
        mbar_init(mbb, 1);
        mbar_init(mbb + 8, 1);
        mbar_arm(mbb, TXB);          // step 0 bulks
        mbar_arm(mbb + 8, TXB);      // step 1 bulks
    }

    // gi walk (warp0 lanes gate their own outputs)
    const int t0    = dir ? TT - 1 : 0;
    const int gstep = dir ? -G3 : G3;
    const float* gp = gid + (size_t)t0 * G3 + jo;
    float gr = 0.f, gz = 0.f, gn = 0.f;
    if (warp == 0) { gr = gp[0]; gz = gp[512]; gn = gp[1024]; }

    float* yp = y_out + (size_t)t0 * 1024 + dir * 512 + jo;
    const int ystep = dir ? -1024 : 1024;

    __syncthreads();
    cluster_sync_();    // mbarriers + h zeros visible cluster-wide

    for (int s = 0; s < TT; s++) {
        const int b = s & 1;

        // ---- phase 1: whole-row partials over the local h slice ----
        ull a0 = 0, a1 = 0, a2 = 0;
        const ull* h2 = (const ull*)hsl[b];
        #pragma unroll
        for (int p = 0; p < 16; p++) {
            ull hv = h2[p];
            FMA2(a0, w[p],      hv);
            FMA2(a1, w[16 + p], hv);
            FMA2(a2, w[32 + p], hv);
        }

        // warp0: prefetch gi for step s+1 (consumed next iter, fully hidden)
        float ngr = 0.f, ngz = 0.f, ngn = 0.f;
        if (warp == 0 && s + 1 < TT) {
            const float* g2 = gp + gstep;
            ngr = g2[0]; ngz = g2[512]; ngn = g2[1024];
        }

        // ---- phase 2: gate-major stage (stride-1 STS); one bulk per warp ----
        {
            float* st = stage[warp][b];
            st[lane]      = lo_f(a0) + hi_f(a0);   // r
            st[32 + lane] = lo_f(a1) + hi_f(a1);   // z
            st[64 + lane] = lo_f(a2) + hi_f(a2);   // n
        }
        __syncwarp();
        if (lane == 0) {
            fence_proxy_async_();
            bulk_push(pbb + (unsigned)((b * 16 + crank) * 384),
                      stgb + (unsigned)((warp * 2 + b) * 384),
                      mbb + (unsigned)(b * 8),
                      (unsigned)warp, 384u);
        }

        // ---- phase 3: warps 0..2 distributed reduce, warp0 gates ----
        if (warp < 3) {
            mbar_wait(mbb + (unsigned)(b * 8), ((unsigned)s >> 1) & 1u);
            if (tid == 0) mbar_arm(mbb + (unsigned)(b * 8), TXB);  // for s+2

            // warp g sums gate g of all 32 outputs (stride-1 LDS)
            const float* pb = &pbuf[b][0][warp * 32 + lane];
            float c0 = 0.f, c1 = 0.f, c2 = 0.f, c3 = 0.f;
            #pragma unroll
            for (int q = 0; q < 4; q++) {
                c0 += pb[(4 * q + 0) * 96];
                c1 += pb[(4 * q + 1) * 96];
                c2 += pb[(4 * q + 2) * 96];
                c3 += pb[(4 * q + 3) * 96];
            }
            const float sg = (c0 + c1) + (c2 + c3);
            if (warp) gsum[warp - 1][lane] = sg;    // z (warp1), n (warp2)
            asm volatile("bar.sync 1, 96;" ::: "memory");

            if (warp == 0) {
                const float sr = sg;
                const float sz = gsum[0][lane];
                const float sn = gsum[1][lane];

                const float hprev = hsl[b][lane];
                float rg = 1.f / (1.f + __expf(-(gr + sr)));
                float zg = 1.f / (1.f + __expf(-(gz + sz)));
                float u  = gn + rg * (sn + bhn);
                float e2 = __expf(2.f * u);
                float ng = 1.f - 2.f / (e2 + 1.f);   // tanh(u), inf-safe
                float hnew = ng + zg * (hprev - ng);

                hsl[b ^ 1][lane] = hnew;
                *yp = hnew;
                if (s == TT - 1) state_out[dir * 512 + jo] = hnew;

                gr = ngr; gz = ngz; gn = ngn;
            }
        }
        gp += gstep; yp += ystep;

        __syncthreads();    // h slice published; stage/pbuf/gsum reuse safe
                            // by the transitive wait-chain argument
    }

    cluster_sync_();    // keep smem alive until all in-flight bulks landed
}

// ---------------- launch ----------------
static void launch_gru(const float* gi,
                       const float* whf, const float* whb,
                       const float* bhf, const float* bhb,
                       float* y_out, float* state_out) {
    cudaFuncSetAttribute(gru_layer_kernel,
                         cudaFuncAttributeNonPortableClusterSizeAllowed, 1);

    cudaLaunchConfig_t cfg = {};
    cfg.gridDim = dim3(32, 1, 1);
    cfg.blockDim = dim3(512, 1, 1);
    cfg.dynamicSmemBytes = 0;
    cfg.stream = 0;
    cudaLaunchAttribute attr[1];
    attr[0].id = cudaLaunchAttributeClusterDimension;
    attr[0].val.clusterDim.x = 16;
    attr[0].val.clusterDim.y = 1;
    attr[0].val.clusterDim.z = 1;
    cfg.attrs = attr;
    cfg.numAttrs = 1;

    cudaLaunchKernelEx(&cfg, gru_layer_kernel, gi, whf, whb, bhf, bhb, y_out, state_out);
}

extern "C" void kernel_launch(void* const* d_in, const int* in_sizes, int n_in,
                              void* d_out, int out_size) {
    const int*   words    = (const int*)d_in[0];
    const float* emb      = (const float*)d_in[1];
    const float* w_ih_l0f = (const float*)d_in[2];
    const float* w_hh_l0f = (const float*)d_in[3];
    const float* b_ih_l0f = (const float*)d_in[4];
    const float* b_hh_l0f = (const float*)d_in[5];
    const float* w_ih_l0b = (const float*)d_in[6];
    const float* w_hh_l0b = (const float*)d_in[7];
    const float* b_ih_l0b = (const float*)d_in[8];
    const float* b_hh_l0b = (const float*)d_in[9];
    const float* w_ih_l1f = (const float*)d_in[10];
    const float* w_hh_l1f = (const float*)d_in[11];
    const float* b_ih_l1f = (const float*)d_in[12];
    const float* b_hh_l1f = (const float*)d_in[13];
    const float* w_ih_l1b = (const float*)d_in[14];
    const float* w_hh_l1b = (const float*)d_in[15];
    const float* b_ih_l1b = (const float*)d_in[16];
    const float* b_hh_l1b = (const float*)d_in[17];
    float* out = (float*)d_out;

    float *px, *py0, *pgi0, *pgi1;
    cudaGetSymbolAddress((void**)&px,   g_x);
    cudaGetSymbolAddress((void**)&py0,  g_y0);
    cudaGetSymbolAddress((void**)&pgi0, g_gi0);
    cudaGetSymbolAddress((void**)&pgi1, g_gi1);

    // 1) embedding
    embed_kernel<<<(TT * EMBD + 255) / 256, 256>>>(words, emb, px);

    // 2) layer-0 input projections (both directions)
    dim3 gg(G3 / BN, TT / BM, 2);
    gemm_gi_kernel<<<gg, 256>>>(px, TT, EMBD,
                                w_ih_l0f, w_ih_l0b,
                                b_ih_l0f, b_hh_l0f, b_ih_l0b, b_hh_l0b, pgi0);

    // 3) layer-0 recurrence
    launch_gru(pgi0, w_hh_l0f, w_hh_l0b, b_hh_l0f, b_hh_l0b,
               py0, out + (size_t)TT * 1024);

    // 4) layer-1 input projections
    gemm_gi_kernel<<<gg, 256>>>(py0, TT, 1024,
                                w_ih_l1f, w_ih_l1b,
                                b_ih_l1f, b_hh_l1f, b_ih_l1b, b_hh_l1b, pgi1);

    // 5) layer-1 recurrence
    launch_gru(pgi1, w_hh_l1f, w_hh_l1b, b_hh_l1f, b_hh_l1b,
               out, out + (size_t)TT * 1024 + 1024);
}